// round 3
// baseline (speedup 1.0000x reference)
#include <cuda_runtime.h>
#include <cstdint>
#include <cstddef>

#define BB 2
#define LL 256
#define DD 512
#define HH 8
#define DVV 64

// ---- scratch (device globals; no allocation allowed) ----
__device__ float g_wrel_c[HH * DD];                    // [h][d]
__device__ float g_value[BB * LL * DD];                // [b][l][h*DV+dv]
__device__ float g_ssrc[BB * HH * LL];                 // [b][h][j]
__device__ float g_stgt[BB * HH * LL];                 // [b][h][i]
__device__ float g_srel[(size_t)BB * LL * LL * HH];    // [(b,i,j)][h]  (4 MB)

// ============================================================
// K1: wrel_c[h][d] = sum_dv W_relation[d, h*64+dv] * w_rel[h,dv]
// grid 16 x 256
// ============================================================
__global__ void k_wrel(const float* __restrict__ Wr, const float* __restrict__ wrel) {
    __shared__ float wr_s[HH * DVV];
    int tid = threadIdx.x;
    wr_s[tid] = wrel[tid];
    wr_s[tid + 256] = wrel[tid + 256];
    __syncthreads();
    int gid = blockIdx.x * 256 + tid;       // 0..4095
    int h = gid & (HH - 1);
    int d = gid >> 3;
    const float4* w4 = (const float4*)(Wr + (size_t)d * DD + h * DVV);
    const float4* s4 = (const float4*)(wr_s + h * DVV);
    float s = 0.f;
#pragma unroll
    for (int t = 0; t < 16; t++) {
        float4 a = w4[t], b = s4[t];
        s += a.x * b.x + a.y * b.y + a.z * b.z + a.w * b.w;
    }
    g_wrel_c[h * DD + d] = s;
}

// ============================================================
// K2: value = inp @ W_value   (512x512x512 fp32 GEMM)
// BM=32, BN=64, BK=32, 128 threads, 4x4 per thread. grid (8,16)
// ============================================================
__global__ void k_value(const float* __restrict__ A, const float* __restrict__ Bm) {
    __shared__ float As[32][33];
    __shared__ float Bs[32][64];
    int tid = threadIdx.x;
    int tx = tid & 15;        // n / 4
    int ty = tid >> 4;        // m / 4 (0..7)
    int m0 = blockIdx.y * 32;
    int n0 = blockIdx.x * 64;
    float acc[4][4] = {};
    for (int k0 = 0; k0 < DD; k0 += 32) {
#pragma unroll
        for (int t = 0; t < 8; t++) {
            int lin = tid + t * 128;
            As[lin & 31][lin >> 5] = A[(size_t)(m0 + (lin >> 5)) * DD + k0 + (lin & 31)];
        }
#pragma unroll
        for (int t = 0; t < 16; t++) {
            int lin = tid + t * 128;
            Bs[lin >> 6][lin & 63] = Bm[(size_t)(k0 + (lin >> 6)) * DD + n0 + (lin & 63)];
        }
        __syncthreads();
#pragma unroll
        for (int k = 0; k < 32; k++) {
            float a0 = As[k][ty * 4 + 0];
            float a1 = As[k][ty * 4 + 1];
            float a2 = As[k][ty * 4 + 2];
            float a3 = As[k][ty * 4 + 3];
            float4 bv = *(const float4*)&Bs[k][tx * 4];
            acc[0][0] += a0 * bv.x; acc[0][1] += a0 * bv.y; acc[0][2] += a0 * bv.z; acc[0][3] += a0 * bv.w;
            acc[1][0] += a1 * bv.x; acc[1][1] += a1 * bv.y; acc[1][2] += a1 * bv.z; acc[1][3] += a1 * bv.w;
            acc[2][0] += a2 * bv.x; acc[2][1] += a2 * bv.y; acc[2][2] += a2 * bv.z; acc[2][3] += a2 * bv.w;
            acc[3][0] += a3 * bv.x; acc[3][1] += a3 * bv.y; acc[3][2] += a3 * bv.z; acc[3][3] += a3 * bv.w;
        }
        __syncthreads();
    }
#pragma unroll
    for (int r = 0; r < 4; r++) {
        float4 v = make_float4(acc[r][0], acc[r][1], acc[r][2], acc[r][3]);
        *(float4*)&g_value[(size_t)(m0 + ty * 4 + r) * DD + n0 + tx * 4] = v;
    }
}

// ============================================================
// K3: s_src[b,h,j] = value[b,h,j,:]·w_src[h],  s_tgt likewise.
// one warp per (b,l). grid 64 x 256
// ============================================================
__global__ void k_srctgt(const float* __restrict__ wsrc, const float* __restrict__ wtgt) {
    int tid = threadIdx.x, warp = tid >> 5, lane = tid & 31;
    int row = blockIdx.x * 8 + warp;              // b*L + l
    const float* vr = g_value + (size_t)row * DD;
    int b = row >> 8, l = row & 255;
#pragma unroll
    for (int h = 0; h < HH; h++) {
        float v1 = vr[h * DVV + lane];
        float v2 = vr[h * DVV + 32 + lane];
        float s = v1 * wsrc[h * DVV + lane] + v2 * wsrc[h * DVV + 32 + lane];
        float t = v1 * wtgt[h * DVV + lane] + v2 * wtgt[h * DVV + 32 + lane];
#pragma unroll
        for (int o = 16; o; o >>= 1) {
            s += __shfl_down_sync(0xffffffffu, s, o);
            t += __shfl_down_sync(0xffffffffu, t, o);
        }
        if (lane == 0) {
            g_ssrc[(b * HH + h) * LL + l] = s;
            g_stgt[(b * HH + h) * LL + l] = t;
        }
    }
}

// ============================================================
// K4 (the HBM-roofline kernel):
// s_rel[(b,i,j)][h] = relation_inp[b,i,j,:] · wrel_c[:,h]
// warp handles 4 rows at a time (amortizes weight smem reads);
// 8 warps/block -> 32 rows/block, grid 4096.
// ============================================================
__global__ void k_srel(const float* __restrict__ rel) {
    __shared__ float4 ws[HH][128];                // wrel_c as float4 [h][d/4]
    int tid = threadIdx.x;
    const float4* wc4 = (const float4*)g_wrel_c;  // 1024 float4
#pragma unroll
    for (int t = 0; t < 4; t++) {
        int idx = tid + t * 256;
        ws[idx >> 7][idx & 127] = wc4[idx];
    }
    __syncthreads();
    int warp = tid >> 5, lane = tid & 31;
    size_t row0 = (size_t)blockIdx.x * 32 + warp * 4;
    const float4* rp = (const float4*)rel;
    float acc[4][HH];
#pragma unroll
    for (int r = 0; r < 4; r++)
#pragma unroll
        for (int h = 0; h < HH; h++) acc[r][h] = 0.f;

#pragma unroll
    for (int p = 0; p < 4; p++) {
        int pos = lane + p * 32;                  // float4 position within row (0..127)
        float4 f0 = rp[(row0 + 0) * 128 + pos];
        float4 f1 = rp[(row0 + 1) * 128 + pos];
        float4 f2 = rp[(row0 + 2) * 128 + pos];
        float4 f3 = rp[(row0 + 3) * 128 + pos];
#pragma unroll
        for (int h = 0; h < HH; h++) {
            float4 w = ws[h][pos];
            acc[0][h] += f0.x * w.x + f0.y * w.y + f0.z * w.z + f0.w * w.w;
            acc[1][h] += f1.x * w.x + f1.y * w.y + f1.z * w.z + f1.w * w.w;
            acc[2][h] += f2.x * w.x + f2.y * w.y + f2.z * w.z + f2.w * w.w;
            acc[3][h] += f3.x * w.x + f3.y * w.y + f3.z * w.z + f3.w * w.w;
        }
    }
#pragma unroll
    for (int r = 0; r < 4; r++) {
        float res[HH];
#pragma unroll
        for (int h = 0; h < HH; h++) {
            float v = acc[r][h];
#pragma unroll
            for (int o = 16; o; o >>= 1) v += __shfl_down_sync(0xffffffffu, v, o);
            res[h] = v;
        }
        if (lane == 0) {
            float4* op = (float4*)(g_srel + (row0 + r) * HH);
            op[0] = make_float4(res[0], res[1], res[2], res[3]);
            op[1] = make_float4(res[4], res[5], res[6], res[7]);
        }
    }
}

// ============================================================
// K5: fused scores -> leaky -> masks -> softmax -> *inv ->
// renorm -> zero-mask -> attn@value -> +inp
// block = (i-tile of 32, h, b). 256 threads. grid (8,8,2).
// dyn smem: vs[256*64] + attn[32*256] + ssrc[256] = 99328 B
// ============================================================
__global__ void k_attn(const float* __restrict__ inp,
                       const int* __restrict__ mask,
                       const float* __restrict__ adj,
                       float* __restrict__ out) {
    extern __shared__ float sm[];
    float* vs = sm;                      // [j][dv], 16384 floats
    float* attn_s = sm + LL * DVV;       // [32][256]
    float* ssrc_s = attn_s + 32 * LL;    // [256]

    int tid = threadIdx.x;
    int it = blockIdx.x, h = blockIdx.y, b = blockIdx.z;

    float4* vs4 = (float4*)vs;
#pragma unroll
    for (int t = 0; t < 16; t++) {
        int idx = tid + t * 256;         // 0..4095 (float4)
        int j = idx >> 4, c = idx & 15;
        vs4[idx] = *(const float4*)(g_value + (size_t)(b * LL + j) * DD + h * DVV + c * 4);
    }
    ssrc_s[tid] = g_ssrc[(b * HH + h) * LL + tid];
    __syncthreads();

    int warp = tid >> 5, lane = tid & 31;
#pragma unroll
    for (int rr = 0; rr < 4; rr++) {
        int rloc = warp * 4 + rr;
        int i = it * 32 + rloc;
        float stgt = g_stgt[(b * HH + h) * LL + i];
        const float* srel_row = g_srel + (size_t)(b * LL + i) * LL * HH + h;
        const int* mrow = mask + (size_t)(b * LL + i) * LL;
        const float* arow = adj + (size_t)((b * HH + h) * LL + i) * LL;

        float sc[8], ac[8];
        unsigned dead = 0;
        float mx = -3.0e38f;
#pragma unroll
        for (int q = 0; q < 8; q++) {
            int j = lane + q * 32;
            float s = ssrc_s[j] + stgt + srel_row[(size_t)j * HH];
            s = (s >= 0.0f) ? s : 0.2f * s;               // leaky relu
            float av = arow[j];
            ac[q] = av;
            if ((mrow[j] != 0) || (av == 0.0f)) {
                s = -1e12f;
                dead |= (1u << q);
            }
            sc[q] = s;
            mx = fmaxf(mx, s);
        }
#pragma unroll
        for (int o = 16; o; o >>= 1) mx = fmaxf(mx, __shfl_xor_sync(0xffffffffu, mx, o));
        float sum = 0.f;
#pragma unroll
        for (int q = 0; q < 8; q++) { sc[q] = __expf(sc[q] - mx); sum += sc[q]; }
#pragma unroll
        for (int o = 16; o; o >>= 1) sum += __shfl_xor_sync(0xffffffffu, sum, o);
        float rsum = 1.0f / sum;
        float asum = 0.f;
#pragma unroll
        for (int q = 0; q < 8; q++) {
            float inv = (ac[q] == 0.0f) ? 1e-12f : 1.0f / ac[q];
            float p = sc[q] * rsum * inv;
            sc[q] = p;
            asum += fabsf(p);
        }
#pragma unroll
        for (int o = 16; o; o >>= 1) asum += __shfl_xor_sync(0xffffffffu, asum, o);
        float rdn = 1.0f / fmaxf(asum, 1e-12f);
#pragma unroll
        for (int q = 0; q < 8; q++) {
            float a = ((dead >> q) & 1u) ? 0.0f : sc[q] * rdn;
            attn_s[rloc * LL + lane + q * 32] = a;
        }
    }
    __syncthreads();

    // phase 2: out[i, dv] = sum_j attn[i][j] * vs[j][dv]
    int dv = tid & 63, g = tid >> 6;     // g: row-group 0..3 (rows g*8..g*8+7)
    float o_[8] = {0.f, 0.f, 0.f, 0.f, 0.f, 0.f, 0.f, 0.f};
    for (int j = 0; j < LL; j += 4) {
        float v0 = vs[(j + 0) * DVV + dv];
        float v1 = vs[(j + 1) * DVV + dv];
        float v2 = vs[(j + 2) * DVV + dv];
        float v3 = vs[(j + 3) * DVV + dv];
#pragma unroll
        for (int r = 0; r < 8; r++) {
            float4 a = *(const float4*)&attn_s[(g * 8 + r) * LL + j];
            o_[r] += a.x * v0 + a.y * v1 + a.z * v2 + a.w * v3;
        }
    }
#pragma unroll
    for (int r = 0; r < 8; r++) {
        int i = it * 32 + g * 8 + r;
        size_t idx = (size_t)(b * LL + i) * DD + h * DVV + dv;
        out[idx] = o_[r] + inp[idx];
    }
}

// ============================================================
extern "C" void kernel_launch(void* const* d_in, const int* in_sizes, int n_in,
                              void* d_out, int out_size) {
    const float* inp  = (const float*)d_in[0];
    const float* rel  = (const float*)d_in[1];
    const int*   mask = (const int*)d_in[2];      // bool serialized as int32
    const float* adj  = (const float*)d_in[3];
    const float* Wv   = (const float*)d_in[4];
    const float* Wr   = (const float*)d_in[5];
    const float* wsrc = (const float*)d_in[6];
    const float* wtgt = (const float*)d_in[7];
    const float* wrel = (const float*)d_in[8];
    float* out = (float*)d_out;

    const int smem_k5 = (LL * DVV + 32 * LL + LL) * (int)sizeof(float);  // 99328
    cudaFuncSetAttribute(k_attn, cudaFuncAttributeMaxDynamicSharedMemorySize, smem_k5);

    k_wrel<<<16, 256>>>(Wr, wrel);
    k_value<<<dim3(8, 16), 128>>>(inp, Wv);
    k_srctgt<<<64, 256>>>(wsrc, wtgt);
    k_srel<<<4096, 256>>>(rel);
    k_attn<<<dim3(8, HH, BB), 256, smem_k5>>>(inp, mask, adj, out);
}

// round 5
// speedup vs baseline: 1.1061x; 1.1061x over previous
#include <cuda_runtime.h>
#include <cstdint>
#include <cstddef>

#define BB 2
#define LL 256
#define DD 512
#define HH 8
#define DVV 64

// ---- scratch (device globals; no allocation allowed) ----
__device__ float g_wrel_c[HH * DD];                    // [h][d]
__device__ float g_value[BB * LL * DD];                // [b][l][h*DV+dv]
__device__ float g_ssrc[BB * HH * LL];                 // [b][h][j]
__device__ float g_stgt[BB * HH * LL];                 // [b][h][i]
__device__ float g_srel[(size_t)BB * HH * LL * LL];    // [b][h][i][j]  (4 MB, transposed)

// ============================================================
// K1: wrel_c[h][d] = sum_dv W_relation[d, h*64+dv] * w_rel[h,dv]
// grid 16 x 256
// ============================================================
__global__ void k_wrel(const float* __restrict__ Wr, const float* __restrict__ wrel) {
    __shared__ float wr_s[HH * DVV];
    int tid = threadIdx.x;
    wr_s[tid] = wrel[tid];
    wr_s[tid + 256] = wrel[tid + 256];
    __syncthreads();
    int gid = blockIdx.x * 256 + tid;       // 0..4095
    int h = gid & (HH - 1);
    int d = gid >> 3;
    const float4* w4 = (const float4*)(Wr + (size_t)d * DD + h * DVV);
    const float4* s4 = (const float4*)(wr_s + h * DVV);
    float s = 0.f;
#pragma unroll
    for (int t = 0; t < 16; t++) {
        float4 a = w4[t], b = s4[t];
        s += a.x * b.x + a.y * b.y + a.z * b.z + a.w * b.w;
    }
    g_wrel_c[h * DD + d] = s;
}

// ============================================================
// K2: value = inp @ W_value  (512x512x512 fp32 GEMM)
// BM=32, BN=64, BK=32, 256 threads (8 warps), 2x4 per thread.
// grid (8,16) = 128 blocks
// ============================================================
__global__ void k_value(const float* __restrict__ A, const float* __restrict__ Bm) {
    __shared__ float As[32][33];
    __shared__ float Bs[32][64];
    int tid = threadIdx.x;
    int tx = tid & 15;        // n / 4
    int ty = tid >> 4;        // m / 2 (0..15)
    int m0 = blockIdx.y * 32;
    int n0 = blockIdx.x * 64;
    float acc[2][4] = {};
    for (int k0 = 0; k0 < DD; k0 += 32) {
#pragma unroll
        for (int t = 0; t < 4; t++) {
            int lin = tid + t * 256;
            As[lin & 31][lin >> 5] = A[(size_t)(m0 + (lin >> 5)) * DD + k0 + (lin & 31)];
        }
#pragma unroll
        for (int t = 0; t < 8; t++) {
            int lin = tid + t * 256;
            Bs[lin >> 6][lin & 63] = Bm[(size_t)(k0 + (lin >> 6)) * DD + n0 + (lin & 63)];
        }
        __syncthreads();
#pragma unroll
        for (int k = 0; k < 32; k++) {
            float a0 = As[k][ty * 2 + 0];
            float a1 = As[k][ty * 2 + 1];
            float4 bv = *(const float4*)&Bs[k][tx * 4];
            acc[0][0] += a0 * bv.x; acc[0][1] += a0 * bv.y; acc[0][2] += a0 * bv.z; acc[0][3] += a0 * bv.w;
            acc[1][0] += a1 * bv.x; acc[1][1] += a1 * bv.y; acc[1][2] += a1 * bv.z; acc[1][3] += a1 * bv.w;
        }
        __syncthreads();
    }
#pragma unroll
    for (int r = 0; r < 2; r++) {
        float4 v = make_float4(acc[r][0], acc[r][1], acc[r][2], acc[r][3]);
        *(float4*)&g_value[(size_t)(m0 + ty * 2 + r) * DD + n0 + tx * 4] = v;
    }
}

// ============================================================
// K3: s_src[b,h,j] = value[b,h,j,:]·w_src[h],  s_tgt likewise.
// one warp per (b,l). grid 64 x 256
// ============================================================
__global__ void k_srctgt(const float* __restrict__ wsrc, const float* __restrict__ wtgt) {
    int tid = threadIdx.x, warp = tid >> 5, lane = tid & 31;
    int row = blockIdx.x * 8 + warp;              // b*L + l
    const float* vr = g_value + (size_t)row * DD;
    int b = row >> 8, l = row & 255;
#pragma unroll
    for (int h = 0; h < HH; h++) {
        float v1 = vr[h * DVV + lane];
        float v2 = vr[h * DVV + 32 + lane];
        float s = v1 * wsrc[h * DVV + lane] + v2 * wsrc[h * DVV + 32 + lane];
        float t = v1 * wtgt[h * DVV + lane] + v2 * wtgt[h * DVV + 32 + lane];
#pragma unroll
        for (int o = 16; o; o >>= 1) {
            s += __shfl_down_sync(0xffffffffu, s, o);
            t += __shfl_down_sync(0xffffffffu, t, o);
        }
        if (lane == 0) {
            g_ssrc[(b * HH + h) * LL + l] = s;
            g_stgt[(b * HH + h) * LL + l] = t;
        }
    }
}

// ============================================================
// K4 (the HBM-roofline kernel):
// s_rel[b,h,i,j] = relation_inp[b,i,j,:] · wrel_c[h,:]
// 4 rows per warp (amortizes weight LDS), float2 chunks to cap
// registers, __launch_bounds__(256,4) -> ~50% occupancy.
// 8 warps/block -> 32 rows/block, grid 4096.
// ============================================================
__global__ void __launch_bounds__(256, 4) k_srel(const float* __restrict__ rel) {
    __shared__ float2 ws2[HH][256];               // wrel_c as float2 [h][d/2]
    int tid = threadIdx.x;
    const float2* wc2 = (const float2*)g_wrel_c;  // 2048 float2
#pragma unroll
    for (int t = 0; t < 8; t++) {
        int idx = tid + t * 256;                  // 0..2047
        ws2[idx >> 8][idx & 255] = wc2[idx];
    }
    __syncthreads();
    int warp = tid >> 5, lane = tid & 31;
    int row0 = blockIdx.x * 32 + warp * 4;        // (b,i,j0): 4 consecutive j
    int b = row0 >> 16, i = (row0 >> 8) & 255, j0 = row0 & 255;
    const float2* r0 = (const float2*)rel + (size_t)row0 * 256 + lane;

    float acc[4][HH];
#pragma unroll
    for (int r = 0; r < 4; r++)
#pragma unroll
        for (int h = 0; h < HH; h++) acc[r][h] = 0.f;

#pragma unroll
    for (int c = 0; c < 8; c++) {                 // 8 chunks of 32 float2
        int pos = lane + c * 32;
        float2 a0 = r0[c * 32];
        float2 a1 = r0[256 + c * 32];
        float2 a2 = r0[512 + c * 32];
        float2 a3 = r0[768 + c * 32];
#pragma unroll
        for (int h = 0; h < HH; h++) {
            float2 w = ws2[h][pos];
            acc[0][h] += a0.x * w.x + a0.y * w.y;
            acc[1][h] += a1.x * w.x + a1.y * w.y;
            acc[2][h] += a2.x * w.x + a2.y * w.y;
            acc[3][h] += a3.x * w.x + a3.y * w.y;
        }
    }

#pragma unroll
    for (int r = 0; r < 4; r++) {
        float res[HH];
#pragma unroll
        for (int h = 0; h < HH; h++) {
            float v = acc[r][h];
#pragma unroll
            for (int o = 16; o; o >>= 1) v += __shfl_xor_sync(0xffffffffu, v, o);
            res[h] = v;                           // all lanes hold sum for head h
        }
        float mine = res[0];
#pragma unroll
        for (int h = 1; h < HH; h++) if (lane == h) mine = res[h];
        if (lane < HH)
            g_srel[(((size_t)b * HH + lane) * LL + i) * LL + (j0 + r)] = mine;
    }
}

// ============================================================
// K5: fused scores -> leaky -> masks -> softmax -> *inv ->
// renorm -> zero-mask -> attn@value -> +inp
// block = (i-tile of 32, h, b). 256 threads. grid (8,8,2).
// dyn smem: vs[256*64] + attn[32*256] + ssrc[256] = 99328 B
// ============================================================
__global__ void k_attn(const float* __restrict__ inp,
                       const int* __restrict__ mask,
                       const float* __restrict__ adj,
                       float* __restrict__ out) {
    extern __shared__ float sm[];
    float* vs = sm;                      // [j][dv], 16384 floats
    float* attn_s = sm + LL * DVV;       // [32][256]
    float* ssrc_s = attn_s + 32 * LL;    // [256]

    int tid = threadIdx.x;
    int it = blockIdx.x, h = blockIdx.y, b = blockIdx.z;

    float4* vs4 = (float4*)vs;
#pragma unroll
    for (int t = 0; t < 16; t++) {
        int idx = tid + t * 256;         // 0..4095 (float4)
        int j = idx >> 4, c = idx & 15;
        vs4[idx] = *(const float4*)(g_value + (size_t)(b * LL + j) * DD + h * DVV + c * 4);
    }
    ssrc_s[tid] = g_ssrc[(b * HH + h) * LL + tid];
    __syncthreads();

    int warp = tid >> 5, lane = tid & 31;
#pragma unroll
    for (int rr = 0; rr < 4; rr++) {
        int rloc = warp * 4 + rr;
        int i = it * 32 + rloc;
        float stgt = g_stgt[(b * HH + h) * LL + i];
        const float* srel_row = g_srel + (((size_t)b * HH + h) * LL + i) * LL;  // coalesced
        const int* mrow = mask + (size_t)(b * LL + i) * LL;
        const float* arow = adj + (size_t)((b * HH + h) * LL + i) * LL;

        float sc[8], ac[8];
        unsigned dead = 0;
        float mx = -3.0e38f;
#pragma unroll
        for (int q = 0; q < 8; q++) {
            int j = lane + q * 32;
            float s = ssrc_s[j] + stgt + srel_row[j];
            s = (s >= 0.0f) ? s : 0.2f * s;               // leaky relu
            float av = arow[j];
            ac[q] = av;
            if ((mrow[j] != 0) || (av == 0.0f)) {
                s = -1e12f;
                dead |= (1u << q);
            }
            sc[q] = s;
            mx = fmaxf(mx, s);
        }
#pragma unroll
        for (int o = 16; o; o >>= 1) mx = fmaxf(mx, __shfl_xor_sync(0xffffffffu, mx, o));
        float sum = 0.f;
#pragma unroll
        for (int q = 0; q < 8; q++) { sc[q] = __expf(sc[q] - mx); sum += sc[q]; }
#pragma unroll
        for (int o = 16; o; o >>= 1) sum += __shfl_xor_sync(0xffffffffu, sum, o);
        float rsum = 1.0f / sum;
        float asum = 0.f;
#pragma unroll
        for (int q = 0; q < 8; q++) {
            float inv = (ac[q] == 0.0f) ? 1e-12f : 1.0f / ac[q];
            float p = sc[q] * rsum * inv;
            sc[q] = p;
            asum += fabsf(p);
        }
#pragma unroll
        for (int o = 16; o; o >>= 1) asum += __shfl_xor_sync(0xffffffffu, asum, o);
        float rdn = 1.0f / fmaxf(asum, 1e-12f);
#pragma unroll
        for (int q = 0; q < 8; q++) {
            float a = ((dead >> q) & 1u) ? 0.0f : sc[q] * rdn;
            attn_s[rloc * LL + lane + q * 32] = a;
        }
    }
    __syncthreads();

    // phase 2: out[i, dv] = sum_j attn[i][j] * vs[j][dv]
    int dv = tid & 63, g = tid >> 6;     // g: row-group 0..3 (rows g*8..g*8+7)
    float o_[8] = {0.f, 0.f, 0.f, 0.f, 0.f, 0.f, 0.f, 0.f};
    for (int j = 0; j < LL; j += 4) {
        float v0 = vs[(j + 0) * DVV + dv];
        float v1 = vs[(j + 1) * DVV + dv];
        float v2 = vs[(j + 2) * DVV + dv];
        float v3 = vs[(j + 3) * DVV + dv];
#pragma unroll
        for (int r = 0; r < 8; r++) {
            float4 a = *(const float4*)&attn_s[(g * 8 + r) * LL + j];
            o_[r] += a.x * v0 + a.y * v1 + a.z * v2 + a.w * v3;
        }
    }
#pragma unroll
    for (int r = 0; r < 8; r++) {
        int i = it * 32 + g * 8 + r;
        size_t idx = (size_t)(b * LL + i) * DD + h * DVV + dv;
        out[idx] = o_[r] + inp[idx];
    }
}

// ============================================================
extern "C" void kernel_launch(void* const* d_in, const int* in_sizes, int n_in,
                              void* d_out, int out_size) {
    const float* inp  = (const float*)d_in[0];
    const float* rel  = (const float*)d_in[1];
    const int*   mask = (const int*)d_in[2];      // bool serialized as int32
    const float* adj  = (const float*)d_in[3];
    const float* Wv   = (const float*)d_in[4];
    const float* Wr   = (const float*)d_in[5];
    const float* wsrc = (const float*)d_in[6];
    const float* wtgt = (const float*)d_in[7];
    const float* wrel = (const float*)d_in[8];
    float* out = (float*)d_out;

    const int smem_k5 = (LL * DVV + 32 * LL + LL) * (int)sizeof(float);  // 99328
    cudaFuncSetAttribute(k_attn, cudaFuncAttributeMaxDynamicSharedMemorySize, smem_k5);

    k_wrel<<<16, 256>>>(Wr, wrel);
    k_value<<<dim3(8, 16), 256>>>(inp, Wv);
    k_srctgt<<<64, 256>>>(wsrc, wtgt);
    k_srel<<<4096, 256>>>(rel);
    k_attn<<<dim3(8, HH, BB), 256, smem_k5>>>(inp, mask, adj, out);
}